// round 12
// baseline (speedup 1.0000x reference)
#include <cuda_runtime.h>
#include <cuda_bf16.h>
#include <cstdint>

// ---------------------------------------------------------------- constants
#define NPTS      65536
#define EDIM      256
#define NEMB      1024
#define PTS_PER_B 1024
#define LAT_B_STRIDE 262144
#define QUANT_ELEMS 16777216

// ---------------------------------------------------------------- scratch
__device__ __nv_bfloat16 g_X[NPTS * EDIM];     // bf16(lat) transposed to [n][d]
__device__ __nv_bfloat16 g_E[NEMB * EDIM];     // bf16(embedding) [k][d]
__device__ float  g_e2[NEMB];
__device__ float  g_x2[NPTS];
__device__ int    g_cand[NPTS * 4];
__device__ double g_loss_sum;

// ---------------------------------------------------------------- helpers
__device__ __forceinline__ uint32_t smem_u32(const void* p) {
    uint32_t a;
    asm("{ .reg .u64 t; cvta.to.shared.u64 t, %1; cvt.u32.u64 %0, t; }" : "=r"(a) : "l"(p));
    return a;
}
__device__ __forceinline__ void cpasync16(uint32_t dst, const void* src) {
    asm volatile("cp.async.cg.shared.global [%0], [%1], 16;" :: "r"(dst), "l"(src));
}
#define CP_COMMIT() asm volatile("cp.async.commit_group;" ::: "memory")
#define CP_WAIT(n)  asm volatile("cp.async.wait_group %0;" :: "n"(n) : "memory")

__device__ __forceinline__ void ldm_x4(uint32_t& r0, uint32_t& r1, uint32_t& r2, uint32_t& r3,
                                       uint32_t addr) {
    asm volatile("ldmatrix.sync.aligned.m8n8.x4.shared.b16 {%0,%1,%2,%3}, [%4];"
        : "=r"(r0), "=r"(r1), "=r"(r2), "=r"(r3) : "r"(addr));
}
__device__ __forceinline__ void mma_bf16(float& c0, float& c1, float& c2, float& c3,
                                         uint32_t a0, uint32_t a1, uint32_t a2, uint32_t a3,
                                         uint32_t b0, uint32_t b1) {
    asm volatile("mma.sync.aligned.m16n8k16.row.col.f32.bf16.bf16.f32 "
        "{%0,%1,%2,%3}, {%4,%5,%6,%7}, {%8,%9}, {%0,%1,%2,%3};"
        : "+f"(c0), "+f"(c1), "+f"(c2), "+f"(c3)
        : "r"(a0), "r"(a1), "r"(a2), "r"(a3), "r"(b0), "r"(b1));
}

// ---------------------------------------------------------------- small kernels
__global__ void k_zero() { g_loss_sum = 0.0; }

__global__ __launch_bounds__(256) void k_prep(const float* __restrict__ emb) {
    int k = blockIdx.x, c = threadIdx.x;
    float v = emb[k * EDIM + c];
    g_E[k * EDIM + c] = __float2bfloat16(v);
    __shared__ float s[256];
    s[c] = v * v;
    __syncthreads();
    for (int o = 128; o > 0; o >>= 1) { if (c < o) s[c] += s[c + o]; __syncthreads(); }
    if (c == 0) g_e2[k] = s[0];
}

// ---------------------------------------------------------------- fused transpose+bf16-convert+x2
#define CPAD 66
#define CONV_SMEM (256 * CPAD * 4)

__global__ __launch_bounds__(256, 3) void k_convX2(const float* __restrict__ lat) {
    extern __shared__ float sF[];
    int n0 = blockIdx.x * 64;
    int b = n0 >> 10, p0 = n0 & 1023;
    int t = threadIdx.x;
    int w = t >> 5, l = t & 31;
    const float* base = lat + (size_t)b * LAT_B_STRIDE + p0;

    int half = l >> 4;
    int pf = l & 15;
#pragma unroll
    for (int r = 0; r < 16; r++) {
        int d = w * 32 + r * 2 + half;
        float4 v = *(const float4*)(base + (size_t)d * PTS_PER_B + pf * 4);
        float* dst = sF + d * CPAD + pf * 4;
        dst[0] = v.x; dst[1] = v.y; dst[2] = v.z; dst[3] = v.w;
    }
    __syncthreads();

    int p = t >> 2, seg = t & 3;
    float s = 0.f;
    uint32_t pk[32];
#pragma unroll
    for (int j = 0; j < 32; j++) {
        float a = sF[(seg * 64 + 2 * j) * CPAD + p];
        float c = sF[(seg * 64 + 2 * j + 1) * CPAD + p];
        s = fmaf(a, a, s);
        s = fmaf(c, c, s);
        unsigned short lo = __bfloat16_as_ushort(__float2bfloat16(a));
        unsigned short hi = __bfloat16_as_ushort(__float2bfloat16(c));
        pk[j] = (uint32_t)lo | ((uint32_t)hi << 16);
    }
    uint4* dst = (uint4*)(g_X + (size_t)(n0 + p) * EDIM + seg * 64);
#pragma unroll
    for (int j = 0; j < 8; j++)
        dst[j] = make_uint4(pk[j * 4], pk[j * 4 + 1], pk[j * 4 + 2], pk[j * 4 + 3]);
    s += __shfl_xor_sync(0xffffffffu, s, 1);
    s += __shfl_xor_sync(0xffffffffu, s, 2);
    if (seg == 0) g_x2[n0 + p] = s;
}

// ---------------------------------------------------------------- bf16 HMMA distance + top-4
// 128 threads (4 warps), warp tile m32 x n32 (full chunk). 2 CTAs/SM.
// smem: X 128x264 bf16 (67584B) + 2 x 32-row E bufs (2x16896B) + e2 (2x128B)
#define ROWB 528
#define XSZ  67584
#define ECH  16896
#define SM_ES   XSZ
#define SM_E2   (SM_ES + 2 * ECH)   // 101376
#define SMEM_P1 (SM_E2 + 256)       // 101632

__global__ __launch_bounds__(128, 2) void k_dist_tc() {
    extern __shared__ char smem[];
    uint32_t sb = smem_u32(smem);
    int tid = threadIdx.x;
    int wid = tid >> 5, l = tid & 31;
    int gid = l >> 2, tig = l & 3;
    int n_base = blockIdx.x * 128;

    // group 0: X tile + E chunk0 + e2 chunk0
    for (int i = tid; i < 4096; i += 128) {
        int row = i >> 5, v = i & 31;
        cpasync16(sb + row * ROWB + v * 16, g_X + (size_t)(n_base + row) * EDIM + v * 8);
    }
    for (int i = tid; i < 1024; i += 128) {
        int row = i >> 5, v = i & 31;
        cpasync16(sb + SM_ES + row * ROWB + v * 16, g_E + (size_t)row * EDIM + v * 8);
    }
    if (tid < 8) cpasync16(sb + SM_E2 + tid * 16, g_e2 + tid * 4);
    CP_COMMIT();
    // group 1: E chunk1
    for (int i = tid; i < 1024; i += 128) {
        int row = i >> 5, v = i & 31;
        cpasync16(sb + SM_ES + ECH + row * ROWB + v * 16, g_E + (size_t)(32 + row) * EDIM + v * 8);
    }
    if (tid < 8) cpasync16(sb + SM_E2 + 128 + tid * 16, g_e2 + 32 + tid * 4);
    CP_COMMIT();

    // ldmatrix offsets: A two m16 frags (warp rows wid*32..+32); B two n16 groups
    uint32_t a_off[2], b_off[2];
#pragma unroll
    for (int mf = 0; mf < 2; mf++)
        a_off[mf] = (uint32_t)((wid * 32 + mf * 16 + (l & 15)) * ROWB + ((l >> 4) & 1) * 16);
#pragma unroll
    for (int jj = 0; jj < 2; jj++)
        b_off[jj] = (uint32_t)((jj * 16 + ((l >> 4) & 1) * 8 + (l & 7)) * ROWB
                               + ((l >> 3) & 1) * 16);

    // top-4 per row-slot: slot g = mf*2+s covers row wid*32+mf*16+s*8+gid
    float bd[4][4]; int bi[4][4];
#pragma unroll
    for (int g = 0; g < 4; g++)
#pragma unroll
        for (int q = 0; q < 4; q++) { bd[g][q] = 3.4e38f; bi[g][q] = 0; }

    for (int c = 0; c < 32; c++) {
        int buf = c & 1;
        if (c < 31) { CP_WAIT(1); } else { CP_WAIT(0); }
        __syncthreads();

        float acc[2][4][4];
#pragma unroll
        for (int mf = 0; mf < 2; mf++)
#pragma unroll
            for (int f = 0; f < 4; f++)
#pragma unroll
                for (int q = 0; q < 4; q++) acc[mf][f][q] = 0.f;

        uint32_t eb = sb + SM_ES + buf * ECH;
#pragma unroll 4
        for (int kc = 0; kc < 16; kc++) {
            uint32_t a[2][4], br[2][4];
#pragma unroll
            for (int mf = 0; mf < 2; mf++)
                ldm_x4(a[mf][0], a[mf][1], a[mf][2], a[mf][3], sb + a_off[mf] + kc * 32);
#pragma unroll
            for (int jj = 0; jj < 2; jj++)
                ldm_x4(br[jj][0], br[jj][1], br[jj][2], br[jj][3], eb + b_off[jj] + kc * 32);
#pragma unroll
            for (int mf = 0; mf < 2; mf++)
#pragma unroll
                for (int jj = 0; jj < 2; jj++)
#pragma unroll
                    for (int h = 0; h < 2; h++)
                        mma_bf16(acc[mf][jj * 2 + h][0], acc[mf][jj * 2 + h][1],
                                 acc[mf][jj * 2 + h][2], acc[mf][jj * 2 + h][3],
                                 a[mf][0], a[mf][1], a[mf][2], a[mf][3],
                                 br[jj][h * 2], br[jj][h * 2 + 1]);
        }

        // epilogue: rank by e2 - 2*dot
        int nck = c * 32;
        const float2* e2p = (const float2*)(smem + SM_E2 + buf * 128);
#pragma unroll
        for (int f = 0; f < 4; f++) {
            int jj = f >> 1, h = f & 1;
            float2 e2v = e2p[jj * 8 + h * 4 + tig];
            int nb0 = nck + jj * 16 + h * 8 + tig * 2;
#pragma unroll
            for (int mf = 0; mf < 2; mf++)
#pragma unroll
                for (int s = 0; s < 2; s++) {
                    int g = mf * 2 + s;
                    float d0 = fmaf(-2.f, acc[mf][f][s * 2 + 0], e2v.x);
                    float d1 = fmaf(-2.f, acc[mf][f][s * 2 + 1], e2v.y);
                    if (d0 < bd[g][3]) {
                        float dv = d0; int iv = nb0;
#pragma unroll
                        for (int q = 0; q < 4; q++)
                            if (dv < bd[g][q]) {
                                float tf = bd[g][q]; int ti = bi[g][q];
                                bd[g][q] = dv; bi[g][q] = iv; dv = tf; iv = ti;
                            }
                    }
                    if (d1 < bd[g][3]) {
                        float dv = d1; int iv = nb0 + 1;
#pragma unroll
                        for (int q = 0; q < 4; q++)
                            if (dv < bd[g][q]) {
                                float tf = bd[g][q]; int ti = bi[g][q];
                                bd[g][q] = dv; bi[g][q] = iv; dv = tf; iv = ti;
                            }
                    }
                }
        }
        __syncthreads();
        if (c + 2 < 32) {
            int nc = c + 2;
            for (int i = tid; i < 1024; i += 128) {
                int row = i >> 5, v = i & 31;
                cpasync16(sb + SM_ES + buf * ECH + row * ROWB + v * 16,
                          g_E + (size_t)(nc * 32 + row) * EDIM + v * 8);
            }
            if (tid < 8) cpasync16(sb + SM_E2 + buf * 128 + tid * 16, g_e2 + nc * 32 + tid * 4);
            CP_COMMIT();
        }
    }

    // merge: each point-row served by 4 tig lanes
    __syncthreads();
    float* sd = (float*)(smem + SM_ES);
    int*   si = (int*)(smem + SM_ES + 8192);
#pragma unroll
    for (int mf = 0; mf < 2; mf++)
#pragma unroll
        for (int s = 0; s < 2; s++) {
            int g = mf * 2 + s;
            int row = wid * 32 + mf * 16 + s * 8 + gid;
#pragma unroll
            for (int q = 0; q < 4; q++) {
                sd[row * 16 + tig * 4 + q] = bd[g][q];
                si[row * 16 + tig * 4 + q] = bi[g][q];
            }
        }
    __syncthreads();
    {
        float fb[4]; int fi[4];
#pragma unroll
        for (int q = 0; q < 4; q++) { fb[q] = 3.4e38f; fi[q] = 0; }
        for (int e = 0; e < 16; e++) {
            float dv = sd[tid * 16 + e]; int iv = si[tid * 16 + e];
            if (dv < fb[3]) {
#pragma unroll
                for (int q = 0; q < 4; q++)
                    if (dv < fb[q]) {
                        float tf = fb[q]; int ti = fi[q];
                        fb[q] = dv; fi[q] = iv; dv = tf; iv = ti;
                    }
            }
        }
#pragma unroll
        for (int q = 0; q < 4; q++) g_cand[(n_base + tid) * 4 + q] = fi[q];
    }
}

// ---------------------------------------------------------------- fused exact re-rank + loss + gather-write
__global__ __launch_bounds__(256) void k_rerank_out(const float* __restrict__ lat,
                                                    const float* __restrict__ emb,
                                                    float* __restrict__ out, int full) {
    int t = threadIdx.x;
    int n = blockIdx.x * 256 + t;
    int b = n >> 10, p = n & 1023;
    size_t base = (size_t)b * LAT_B_STRIDE + p;
    const float* lp = lat + base;
    int c0 = g_cand[n * 4 + 0], c1 = g_cand[n * 4 + 1];
    int c2 = g_cand[n * 4 + 2], c3 = g_cand[n * 4 + 3];
    const float* e0 = emb + (size_t)c0 * EDIM;
    const float* e1 = emb + (size_t)c1 * EDIM;
    const float* e2p = emb + (size_t)c2 * EDIM;
    const float* e3 = emb + (size_t)c3 * EDIM;
    float d0 = 0.f, d1 = 0.f, d2 = 0.f, d3 = 0.f;
#pragma unroll 4
    for (int d = 0; d < EDIM; d++) {
        float x = lp[(size_t)d * PTS_PER_B];
        d0 = fmaf(x, e0[d], d0);
        d1 = fmaf(x, e1[d], d1);
        d2 = fmaf(x, e2p[d], d2);
        d3 = fmaf(x, e3[d], d3);
    }
    float x2 = g_x2[n];
    float best = 3.4e38f; int bk = 0x7fffffff;
    float dd; int kk;
    dd = __fsub_rn(__fadd_rn(x2, g_e2[c0]), __fmul_rn(2.f, d0)); kk = c0;
    if (dd < best || (dd == best && kk < bk)) { best = dd; bk = kk; }
    dd = __fsub_rn(__fadd_rn(x2, g_e2[c1]), __fmul_rn(2.f, d1)); kk = c1;
    if (dd < best || (dd == best && kk < bk)) { best = dd; bk = kk; }
    dd = __fsub_rn(__fadd_rn(x2, g_e2[c2]), __fmul_rn(2.f, d2)); kk = c2;
    if (dd < best || (dd == best && kk < bk)) { best = dd; bk = kk; }
    dd = __fsub_rn(__fadd_rn(x2, g_e2[c3]), __fmul_rn(2.f, d3)); kk = c3;
    if (dd < best || (dd == best && kk < bk)) { best = dd; bk = kk; }
    if (full) out[QUANT_ELEMS + 1 + n] = (float)bk;

    // quant write from embedding ROW (thread-sequential, L1-line reuse)
    const float* eb = emb + (size_t)bk * EDIM;
#pragma unroll 4
    for (int c = 0; c < EDIM; c++)
        out[base + (size_t)c * PTS_PER_B] = eb[c];

    __shared__ double s[256];
    s[t] = (double)best;
    __syncthreads();
    for (int o = 128; o > 0; o >>= 1) { if (t < o) s[t] += s[t + o]; __syncthreads(); }
    if (t == 0) atomicAdd(&g_loss_sum, s[0]);
}

__global__ void k_fin(float* out) {
    float m = (float)(g_loss_sum * (1.0 / (double)QUANT_ELEMS));
    out[QUANT_ELEMS] = __fadd_rn(m, __fmul_rn(0.25f, m));
}

// ---------------------------------------------------------------- launch
extern "C" void kernel_launch(void* const* d_in, const int* in_sizes, int n_in,
                              void* d_out, int out_size) {
    const float* lat = (const float*)d_in[0];
    const float* emb = (const float*)d_in[1];
    float* out = (float*)d_out;
    int full = (out_size >= QUANT_ELEMS + 1 + NPTS) ? 1 : 0;

    cudaFuncSetAttribute(k_dist_tc, cudaFuncAttributeMaxDynamicSharedMemorySize, SMEM_P1);
    cudaFuncSetAttribute(k_convX2, cudaFuncAttributeMaxDynamicSharedMemorySize, CONV_SMEM);

    k_zero<<<1, 1>>>();                                     // 0
    k_prep<<<NEMB, 256>>>(emb);                             // 1
    k_convX2<<<NPTS / 64, 256, CONV_SMEM>>>(lat);           // 2
    k_dist_tc<<<NPTS / 128, 128, SMEM_P1>>>();              // 3  <- profile slot
    k_rerank_out<<<NPTS / 256, 256>>>(lat, emb, out, full); // 4
    if (full) k_fin<<<1, 1>>>(out);                         // 5
}

// round 14
// speedup vs baseline: 1.1572x; 1.1572x over previous
#include <cuda_runtime.h>
#include <cuda_bf16.h>
#include <cstdint>

// ---------------------------------------------------------------- constants
#define NPTS      65536
#define EDIM      256
#define NEMB      1024
#define PTS_PER_B 1024
#define LAT_B_STRIDE 262144
#define QUANT_ELEMS 16777216

// ---------------------------------------------------------------- scratch
__device__ __nv_bfloat16 g_X[NPTS * EDIM];     // bf16(lat) transposed to [n][d]
__device__ __nv_bfloat16 g_E[NEMB * EDIM];     // bf16(embedding) [k][d]
__device__ float  g_eT[EDIM * NEMB];           // fp32 embedding transposed [d][k]
__device__ float  g_e2[NEMB];
__device__ float  g_x2[NPTS];
__device__ int    g_cand[NPTS * 4];
__device__ double g_loss_sum;

// ---------------------------------------------------------------- helpers
__device__ __forceinline__ uint32_t smem_u32(const void* p) {
    uint32_t a;
    asm("{ .reg .u64 t; cvta.to.shared.u64 t, %1; cvt.u32.u64 %0, t; }" : "=r"(a) : "l"(p));
    return a;
}
__device__ __forceinline__ void cpasync16(uint32_t dst, const void* src) {
    asm volatile("cp.async.cg.shared.global [%0], [%1], 16;" :: "r"(dst), "l"(src));
}
#define CP_COMMIT() asm volatile("cp.async.commit_group;" ::: "memory")
#define CP_WAIT(n)  asm volatile("cp.async.wait_group %0;" :: "n"(n) : "memory")

__device__ __forceinline__ void ldm_x4(uint32_t& r0, uint32_t& r1, uint32_t& r2, uint32_t& r3,
                                       uint32_t addr) {
    asm volatile("ldmatrix.sync.aligned.m8n8.x4.shared.b16 {%0,%1,%2,%3}, [%4];"
        : "=r"(r0), "=r"(r1), "=r"(r2), "=r"(r3) : "r"(addr));
}
__device__ __forceinline__ void mma_bf16(float& c0, float& c1, float& c2, float& c3,
                                         uint32_t a0, uint32_t a1, uint32_t a2, uint32_t a3,
                                         uint32_t b0, uint32_t b1) {
    asm volatile("mma.sync.aligned.m16n8k16.row.col.f32.bf16.bf16.f32 "
        "{%0,%1,%2,%3}, {%4,%5,%6,%7}, {%8,%9}, {%0,%1,%2,%3};"
        : "+f"(c0), "+f"(c1), "+f"(c2), "+f"(c3)
        : "r"(a0), "r"(a1), "r"(a2), "r"(a3), "r"(b0), "r"(b1));
}

// ---------------------------------------------------------------- small kernels
__global__ void k_zero() { g_loss_sum = 0.0; }

__global__ __launch_bounds__(256) void k_prep(const float* __restrict__ emb) {
    int k = blockIdx.x, c = threadIdx.x;
    float v = emb[k * EDIM + c];
    g_eT[c * NEMB + k] = v;
    g_E[k * EDIM + c] = __float2bfloat16(v);
    __shared__ float s[256];
    s[c] = v * v;
    __syncthreads();
    for (int o = 128; o > 0; o >>= 1) { if (c < o) s[c] += s[c + o]; __syncthreads(); }
    if (c == 0) g_e2[k] = s[0];
}

// ---------------------------------------------------------------- fused transpose+bf16-convert+x2
#define CPAD 66
#define CONV_SMEM (256 * CPAD * 4)

__global__ __launch_bounds__(256, 3) void k_convX2(const float* __restrict__ lat) {
    extern __shared__ float sF[];
    int n0 = blockIdx.x * 64;
    int b = n0 >> 10, p0 = n0 & 1023;
    int t = threadIdx.x;
    int w = t >> 5, l = t & 31;
    const float* base = lat + (size_t)b * LAT_B_STRIDE + p0;

    int half = l >> 4;
    int pf = l & 15;
#pragma unroll
    for (int r = 0; r < 16; r++) {
        int d = w * 32 + r * 2 + half;
        float4 v = *(const float4*)(base + (size_t)d * PTS_PER_B + pf * 4);
        float* dst = sF + d * CPAD + pf * 4;
        dst[0] = v.x; dst[1] = v.y; dst[2] = v.z; dst[3] = v.w;
    }
    __syncthreads();

    int p = t >> 2, seg = t & 3;
    float s = 0.f;
    uint32_t pk[32];
#pragma unroll
    for (int j = 0; j < 32; j++) {
        int jp = (j + seg * 2) & 31;   // seg-stagger: distinct banks across segs
        float a = sF[(seg * 64 + 2 * jp) * CPAD + p];
        float c = sF[(seg * 64 + 2 * jp + 1) * CPAD + p];
        s = fmaf(a, a, s);
        s = fmaf(c, c, s);
        unsigned short lo = __bfloat16_as_ushort(__float2bfloat16(a));
        unsigned short hi = __bfloat16_as_ushort(__float2bfloat16(c));
        pk[jp] = (uint32_t)lo | ((uint32_t)hi << 16);
    }
    uint4* dst = (uint4*)(g_X + (size_t)(n0 + p) * EDIM + seg * 64);
#pragma unroll
    for (int j = 0; j < 8; j++)
        dst[j] = make_uint4(pk[j * 4], pk[j * 4 + 1], pk[j * 4 + 2], pk[j * 4 + 3]);
    s += __shfl_xor_sync(0xffffffffu, s, 1);
    s += __shfl_xor_sync(0xffffffffu, s, 2);
    if (seg == 0) g_x2[n0 + p] = s;
}

// ---------------------------------------------------------------- bf16 HMMA distance + top-4
// 256 threads (8 warps, warp = m16 rows), A held in registers for full K=256.
// smem: 4-deep E chunk ring (4 x 32 x 528B) + e2 ring (4 x 128B). 2 CTAs/SM.
#define ROWB 528
#define ECH  16896
#define SM_E2   (4 * ECH)           // 67584
#define SMEM_P1 (SM_E2 + 512)       // 68096

__global__ __launch_bounds__(256, 2) void k_dist_tc() {
    extern __shared__ char smem[];
    uint32_t sb = smem_u32(smem);
    int tid = threadIdx.x;
    int wid = tid >> 5, l = tid & 31;
    int gid = l >> 2, tig = l & 3;
    int n_base = blockIdx.x * 128;

    // prologue: issue E chunks 0..3
#pragma unroll
    for (int pc = 0; pc < 4; pc++) {
        for (int i = tid; i < 1024; i += 256) {
            int row = i >> 5, v = i & 31;
            cpasync16(sb + pc * ECH + row * ROWB + v * 16,
                      g_E + (size_t)(pc * 32 + row) * EDIM + v * 8);
        }
        if (tid < 8) cpasync16(sb + SM_E2 + pc * 128 + tid * 16, g_e2 + pc * 32 + tid * 4);
        CP_COMMIT();
    }

    // A fragments for this warp's m16 rows, all K=256, direct from gmem.
    // mma m16n8k16 A layout: lane l: reg0=(r, c), reg1=(r+8, c), reg2=(r, c+8), reg3=(r+8, c+8)
    // with r = l>>2, c = (l&3)*2  (bf16 cols; pair load = 4 bytes)
    uint32_t a[16][4];
    {
        const char* arow = (const char*)(g_X + (size_t)(n_base + wid * 16) * EDIM);
        int r = l >> 2;
        int cb = (l & 3) * 4;     // byte offset of col pair
#pragma unroll
        for (int kc = 0; kc < 16; kc++) {
            const char* p0 = arow + r * 512 + kc * 32 + cb;
            a[kc][0] = *(const uint32_t*)(p0);
            a[kc][1] = *(const uint32_t*)(p0 + 8 * 512);
            a[kc][2] = *(const uint32_t*)(p0 + 16);
            a[kc][3] = *(const uint32_t*)(p0 + 8 * 512 + 16);
        }
    }

    uint32_t b_off[2];
#pragma unroll
    for (int jj = 0; jj < 2; jj++)
        b_off[jj] = (uint32_t)((jj * 16 + ((l >> 4) & 1) * 8 + (l & 7)) * ROWB
                               + ((l >> 3) & 1) * 16);

    float bd[2][4]; int bi[2][4];
#pragma unroll
    for (int s = 0; s < 2; s++)
#pragma unroll
        for (int q = 0; q < 4; q++) { bd[s][q] = 3.4e38f; bi[s][q] = 0; }

    for (int c = 0; c < 32; c++) {
        int buf = c & 3;
        if (c <= 28) { CP_WAIT(3); }
        else if (c == 29) { CP_WAIT(2); }
        else if (c == 30) { CP_WAIT(1); }
        else { CP_WAIT(0); }
        __syncthreads();

        float acc[4][4];
#pragma unroll
        for (int jt = 0; jt < 4; jt++)
#pragma unroll
            for (int q = 0; q < 4; q++) acc[jt][q] = 0.f;

        uint32_t eb = sb + buf * ECH;
#pragma unroll
        for (int kc = 0; kc < 16; kc++) {
            uint32_t br[2][4];
#pragma unroll
            for (int jj = 0; jj < 2; jj++)
                ldm_x4(br[jj][0], br[jj][1], br[jj][2], br[jj][3], eb + b_off[jj] + kc * 32);
#pragma unroll
            for (int jj = 0; jj < 2; jj++)
#pragma unroll
                for (int h = 0; h < 2; h++)
                    mma_bf16(acc[jj * 2 + h][0], acc[jj * 2 + h][1],
                             acc[jj * 2 + h][2], acc[jj * 2 + h][3],
                             a[kc][0], a[kc][1], a[kc][2], a[kc][3],
                             br[jj][h * 2], br[jj][h * 2 + 1]);
        }

        // epilogue: rank by e2 - 2*dot (x2 per-point constant)
        int nck = c * 32;
        const float2* e2p = (const float2*)(smem + SM_E2 + buf * 128);
#pragma unroll
        for (int jt = 0; jt < 4; jt++) {
            float2 e2v = e2p[jt * 4 + tig];
            int nb0 = nck + jt * 8 + tig * 2;
#pragma unroll
            for (int s = 0; s < 2; s++) {
                float d0 = fmaf(-2.f, acc[jt][s * 2 + 0], e2v.x);
                float d1 = fmaf(-2.f, acc[jt][s * 2 + 1], e2v.y);
                if (d0 < bd[s][3]) {
                    float dv = d0; int iv = nb0;
#pragma unroll
                    for (int q = 0; q < 4; q++)
                        if (dv < bd[s][q]) {
                            float tf = bd[s][q]; int ti = bi[s][q];
                            bd[s][q] = dv; bi[s][q] = iv; dv = tf; iv = ti;
                        }
                }
                if (d1 < bd[s][3]) {
                    float dv = d1; int iv = nb0 + 1;
#pragma unroll
                    for (int q = 0; q < 4; q++)
                        if (dv < bd[s][q]) {
                            float tf = bd[s][q]; int ti = bi[s][q];
                            bd[s][q] = dv; bi[s][q] = iv; dv = tf; iv = ti;
                        }
                }
            }
        }
        __syncthreads();                 // everyone done reading buf
        int nc = c + 4;
        if (nc < 32) {                   // refill this buffer slot
            for (int i = tid; i < 1024; i += 256) {
                int row = i >> 5, v = i & 31;
                cpasync16(sb + buf * ECH + row * ROWB + v * 16,
                          g_E + (size_t)(nc * 32 + row) * EDIM + v * 8);
            }
            if (tid < 8) cpasync16(sb + SM_E2 + buf * 128 + tid * 16, g_e2 + nc * 32 + tid * 4);
            CP_COMMIT();
        }
    }

    // merge per-row top-4 across the 4 tig lanes (reuse E smem)
    __syncthreads();
    float* sd = (float*)(smem);
    int*   si = (int*)(smem + 8192);
#pragma unroll
    for (int s = 0; s < 2; s++) {
        int row = wid * 16 + s * 8 + gid;
#pragma unroll
        for (int q = 0; q < 4; q++) {
            sd[row * 16 + tig * 4 + q] = bd[s][q];
            si[row * 16 + tig * 4 + q] = bi[s][q];
        }
    }
    __syncthreads();
    if (tid < 128) {
        float fb[4]; int fi[4];
#pragma unroll
        for (int q = 0; q < 4; q++) { fb[q] = 3.4e38f; fi[q] = 0; }
        for (int e = 0; e < 16; e++) {
            float dv = sd[tid * 16 + e]; int iv = si[tid * 16 + e];
            if (dv < fb[3]) {
#pragma unroll
                for (int q = 0; q < 4; q++)
                    if (dv < fb[q]) {
                        float tf = fb[q]; int ti = fi[q];
                        fb[q] = dv; fi[q] = iv; dv = tf; iv = ti;
                    }
            }
        }
#pragma unroll
        for (int q = 0; q < 4; q++) g_cand[(n_base + tid) * 4 + q] = fi[q];
    }
}

// ---------------------------------------------------------------- fused exact re-rank + loss + gather-write
__global__ __launch_bounds__(256) void k_rerank_out(const float* __restrict__ lat,
                                                    const float* __restrict__ emb,
                                                    float* __restrict__ out, int full) {
    int t = threadIdx.x;
    int n = blockIdx.x * 256 + t;
    int b = n >> 10, p = n & 1023;
    size_t base = (size_t)b * LAT_B_STRIDE + p;
    const float* lp = lat + base;
    int c0 = g_cand[n * 4 + 0], c1 = g_cand[n * 4 + 1];
    int c2 = g_cand[n * 4 + 2], c3 = g_cand[n * 4 + 3];
    const float* e0 = emb + (size_t)c0 * EDIM;
    const float* e1 = emb + (size_t)c1 * EDIM;
    const float* e2p = emb + (size_t)c2 * EDIM;
    const float* e3 = emb + (size_t)c3 * EDIM;
    float d0 = 0.f, d1 = 0.f, d2 = 0.f, d3 = 0.f;
#pragma unroll 4
    for (int d = 0; d < EDIM; d++) {
        float x = lp[(size_t)d * PTS_PER_B];
        d0 = fmaf(x, e0[d], d0);
        d1 = fmaf(x, e1[d], d1);
        d2 = fmaf(x, e2p[d], d2);
        d3 = fmaf(x, e3[d], d3);
    }
    float x2 = g_x2[n];
    float best = 3.4e38f; int bk = 0x7fffffff;
    float dd; int kk;
    dd = __fsub_rn(__fadd_rn(x2, g_e2[c0]), __fmul_rn(2.f, d0)); kk = c0;
    if (dd < best || (dd == best && kk < bk)) { best = dd; bk = kk; }
    dd = __fsub_rn(__fadd_rn(x2, g_e2[c1]), __fmul_rn(2.f, d1)); kk = c1;
    if (dd < best || (dd == best && kk < bk)) { best = dd; bk = kk; }
    dd = __fsub_rn(__fadd_rn(x2, g_e2[c2]), __fmul_rn(2.f, d2)); kk = c2;
    if (dd < best || (dd == best && kk < bk)) { best = dd; bk = kk; }
    dd = __fsub_rn(__fadd_rn(x2, g_e2[c3]), __fmul_rn(2.f, d3)); kk = c3;
    if (dd < best || (dd == best && kk < bk)) { best = dd; bk = kk; }
    if (full) out[QUANT_ELEMS + 1 + n] = (float)bk;

    // quant write: gather eT columns (R10-measured layout)
#pragma unroll 4
    for (int c = 0; c < EDIM; c++)
        out[base + (size_t)c * PTS_PER_B] = g_eT[c * NEMB + bk];

    __shared__ double s[256];
    s[t] = (double)best;
    __syncthreads();
    for (int o = 128; o > 0; o >>= 1) { if (t < o) s[t] += s[t + o]; __syncthreads(); }
    if (t == 0) atomicAdd(&g_loss_sum, s[0]);
}

__global__ void k_fin(float* out) {
    float m = (float)(g_loss_sum * (1.0 / (double)QUANT_ELEMS));
    out[QUANT_ELEMS] = __fadd_rn(m, __fmul_rn(0.25f, m));
}

// ---------------------------------------------------------------- launch
extern "C" void kernel_launch(void* const* d_in, const int* in_sizes, int n_in,
                              void* d_out, int out_size) {
    const float* lat = (const float*)d_in[0];
    const float* emb = (const float*)d_in[1];
    float* out = (float*)d_out;
    int full = (out_size >= QUANT_ELEMS + 1 + NPTS) ? 1 : 0;

    cudaFuncSetAttribute(k_dist_tc, cudaFuncAttributeMaxDynamicSharedMemorySize, SMEM_P1);
    cudaFuncSetAttribute(k_convX2, cudaFuncAttributeMaxDynamicSharedMemorySize, CONV_SMEM);

    k_zero<<<1, 1>>>();                                     // 0
    k_prep<<<NEMB, 256>>>(emb);                             // 1
    k_convX2<<<NPTS / 64, 256, CONV_SMEM>>>(lat);           // 2
    k_dist_tc<<<NPTS / 128, 256, SMEM_P1>>>();              // 3  <- profile slot
    k_rerank_out<<<NPTS / 256, 256>>>(lat, emb, out, full); // 4
    if (full) k_fin<<<1, 1>>>(out);                         // 5
}

// round 15
// speedup vs baseline: 1.1608x; 1.0032x over previous
#include <cuda_runtime.h>
#include <cuda_bf16.h>
#include <cstdint>

// ---------------------------------------------------------------- constants
#define NPTS      65536
#define EDIM      256
#define NEMB      1024
#define PTS_PER_B 1024
#define LAT_B_STRIDE 262144
#define QUANT_ELEMS 16777216

// ---------------------------------------------------------------- scratch
__device__ __nv_bfloat16 g_E[NEMB * EDIM];     // bf16(embedding) [k][d]
__device__ float  g_e2[NEMB];
__device__ double g_loss_sum;

// ---------------------------------------------------------------- helpers
__device__ __forceinline__ uint32_t smem_u32(const void* p) {
    uint32_t a;
    asm("{ .reg .u64 t; cvta.to.shared.u64 t, %1; cvt.u32.u64 %0, t; }" : "=r"(a) : "l"(p));
    return a;
}
__device__ __forceinline__ void cpasync16(uint32_t dst, const void* src) {
    asm volatile("cp.async.cg.shared.global [%0], [%1], 16;" :: "r"(dst), "l"(src));
}
#define CP_COMMIT() asm volatile("cp.async.commit_group;" ::: "memory")
#define CP_WAIT(n)  asm volatile("cp.async.wait_group %0;" :: "n"(n) : "memory")

__device__ __forceinline__ void ldm_x4(uint32_t& r0, uint32_t& r1, uint32_t& r2, uint32_t& r3,
                                       uint32_t addr) {
    asm volatile("ldmatrix.sync.aligned.m8n8.x4.shared.b16 {%0,%1,%2,%3}, [%4];"
        : "=r"(r0), "=r"(r1), "=r"(r2), "=r"(r3) : "r"(addr));
}
__device__ __forceinline__ void mma_bf16(float& c0, float& c1, float& c2, float& c3,
                                         uint32_t a0, uint32_t a1, uint32_t a2, uint32_t a3,
                                         uint32_t b0, uint32_t b1) {
    asm volatile("mma.sync.aligned.m16n8k16.row.col.f32.bf16.bf16.f32 "
        "{%0,%1,%2,%3}, {%4,%5,%6,%7}, {%8,%9}, {%0,%1,%2,%3};"
        : "+f"(c0), "+f"(c1), "+f"(c2), "+f"(c3)
        : "r"(a0), "r"(a1), "r"(a2), "r"(a3), "r"(b0), "r"(b1));
}
__device__ __forceinline__ uint32_t pack_bf16(float lo, float hi) {
    return (uint32_t)__bfloat16_as_ushort(__float2bfloat16(lo))
         | ((uint32_t)__bfloat16_as_ushort(__float2bfloat16(hi)) << 16);
}

// ---------------------------------------------------------------- small kernels
__global__ void k_zero() { g_loss_sum = 0.0; }

__global__ __launch_bounds__(256) void k_prep(const float* __restrict__ emb) {
    int k = blockIdx.x, c = threadIdx.x;
    float v = emb[k * EDIM + c];
    g_E[k * EDIM + c] = __float2bfloat16(v);
    __shared__ float s[256];
    s[c] = v * v;
    __syncthreads();
    for (int o = 128; o > 0; o >>= 1) { if (c < o) s[c] += s[c + o]; __syncthreads(); }
    if (c == 0) g_e2[k] = s[0];
}

// ---------------------------------------------------------------- fused mega-kernel
// 256 threads (8 warps, warp = m16 rows), A regs from lat directly, 4-deep E ring,
// top-4 candidates -> exact fp32 rerank + quant/idx write + loss. 2 CTAs/SM.
#define ROWB 528
#define ECH  16896
#define SM_E2   (4 * ECH)           // 67584
#define SMEM_P1 (SM_E2 + 512)       // 68096

__global__ __launch_bounds__(256, 2) void k_dist_tc(const float* __restrict__ lat,
                                                    const float* __restrict__ emb,
                                                    float* __restrict__ out, int full) {
    extern __shared__ char smem[];
    uint32_t sb = smem_u32(smem);
    int tid = threadIdx.x;
    int wid = tid >> 5, l = tid & 31;
    int gid = l >> 2, tig = l & 3;
    int n_base = blockIdx.x * 128;
    int b = n_base >> 10, p0 = n_base & 1023;
    const float* latb = lat + (size_t)b * LAT_B_STRIDE + p0;

    // prologue: issue E chunks 0..3
#pragma unroll
    for (int pc = 0; pc < 4; pc++) {
        for (int i = tid; i < 1024; i += 256) {
            int row = i >> 5, v = i & 31;
            cpasync16(sb + pc * ECH + row * ROWB + v * 16,
                      g_E + (size_t)(pc * 32 + row) * EDIM + v * 8);
        }
        if (tid < 8) cpasync16(sb + SM_E2 + pc * 128 + tid * 16, g_e2 + pc * 32 + tid * 4);
        CP_COMMIT();
    }

    // A fragments straight from fp32 lat (convert to bf16 pairs).
    // frag reg j for lane l: j0=(r,c0), j1=(r+8,c0), j2=(r,c0+8), j3=(r+8,c0+8);
    // element (m, c) lives at latb[c*1024 + m], m = wid*16 + r (+8).
    uint32_t a[16][4];
    {
        int r = l >> 2;
        int c0 = (l & 3) * 2;
        int m0 = wid * 16 + r;
#pragma unroll
        for (int kc = 0; kc < 16; kc++) {
            int cb = kc * 16 + c0;
            float f00 = latb[(size_t)(cb    ) * PTS_PER_B + m0];
            float f01 = latb[(size_t)(cb + 1) * PTS_PER_B + m0];
            float f10 = latb[(size_t)(cb    ) * PTS_PER_B + m0 + 8];
            float f11 = latb[(size_t)(cb + 1) * PTS_PER_B + m0 + 8];
            float f20 = latb[(size_t)(cb + 8) * PTS_PER_B + m0];
            float f21 = latb[(size_t)(cb + 9) * PTS_PER_B + m0];
            float f30 = latb[(size_t)(cb + 8) * PTS_PER_B + m0 + 8];
            float f31 = latb[(size_t)(cb + 9) * PTS_PER_B + m0 + 8];
            a[kc][0] = pack_bf16(f00, f01);
            a[kc][1] = pack_bf16(f10, f11);
            a[kc][2] = pack_bf16(f20, f21);
            a[kc][3] = pack_bf16(f30, f31);
        }
    }

    uint32_t b_off[2];
#pragma unroll
    for (int jj = 0; jj < 2; jj++)
        b_off[jj] = (uint32_t)((jj * 16 + ((l >> 4) & 1) * 8 + (l & 7)) * ROWB
                               + ((l >> 3) & 1) * 16);

    float bd[2][4]; int bi[2][4];
#pragma unroll
    for (int s = 0; s < 2; s++)
#pragma unroll
        for (int q = 0; q < 4; q++) { bd[s][q] = 3.4e38f; bi[s][q] = 0; }

    for (int c = 0; c < 32; c++) {
        int buf = c & 3;
        if (c <= 28) { CP_WAIT(3); }
        else if (c == 29) { CP_WAIT(2); }
        else if (c == 30) { CP_WAIT(1); }
        else { CP_WAIT(0); }
        __syncthreads();

        float acc[4][4];
#pragma unroll
        for (int jt = 0; jt < 4; jt++)
#pragma unroll
            for (int q = 0; q < 4; q++) acc[jt][q] = 0.f;

        uint32_t eb = sb + buf * ECH;
#pragma unroll
        for (int kc = 0; kc < 16; kc++) {
            uint32_t br[2][4];
#pragma unroll
            for (int jj = 0; jj < 2; jj++)
                ldm_x4(br[jj][0], br[jj][1], br[jj][2], br[jj][3], eb + b_off[jj] + kc * 32);
#pragma unroll
            for (int jj = 0; jj < 2; jj++)
#pragma unroll
                for (int h = 0; h < 2; h++)
                    mma_bf16(acc[jj * 2 + h][0], acc[jj * 2 + h][1],
                             acc[jj * 2 + h][2], acc[jj * 2 + h][3],
                             a[kc][0], a[kc][1], a[kc][2], a[kc][3],
                             br[jj][h * 2], br[jj][h * 2 + 1]);
        }

        // rank by e2 - 2*dot (x2 per-point constant)
        int nck = c * 32;
        const float2* e2p = (const float2*)(smem + SM_E2 + buf * 128);
#pragma unroll
        for (int jt = 0; jt < 4; jt++) {
            float2 e2v = e2p[jt * 4 + tig];
            int nb0 = nck + jt * 8 + tig * 2;
#pragma unroll
            for (int s = 0; s < 2; s++) {
                float d0 = fmaf(-2.f, acc[jt][s * 2 + 0], e2v.x);
                float d1 = fmaf(-2.f, acc[jt][s * 2 + 1], e2v.y);
                if (d0 < bd[s][3]) {
                    float dv = d0; int iv = nb0;
#pragma unroll
                    for (int q = 0; q < 4; q++)
                        if (dv < bd[s][q]) {
                            float tf = bd[s][q]; int ti = bi[s][q];
                            bd[s][q] = dv; bi[s][q] = iv; dv = tf; iv = ti;
                        }
                }
                if (d1 < bd[s][3]) {
                    float dv = d1; int iv = nb0 + 1;
#pragma unroll
                    for (int q = 0; q < 4; q++)
                        if (dv < bd[s][q]) {
                            float tf = bd[s][q]; int ti = bi[s][q];
                            bd[s][q] = dv; bi[s][q] = iv; dv = tf; iv = ti;
                        }
                }
            }
        }
        __syncthreads();
        int nc = c + 4;
        if (nc < 32) {
            for (int i = tid; i < 1024; i += 256) {
                int row = i >> 5, v = i & 31;
                cpasync16(sb + buf * ECH + row * ROWB + v * 16,
                          g_E + (size_t)(nc * 32 + row) * EDIM + v * 8);
            }
            if (tid < 8) cpasync16(sb + SM_E2 + buf * 128 + tid * 16, g_e2 + nc * 32 + tid * 4);
            CP_COMMIT();
        }
    }

    // ---- merge per-row top-4 across the 4 tig lanes
    __syncthreads();
    float* sd   = (float*)(smem);
    int*   si   = (int*)(smem + 8192);
    int*   scand = (int*)(smem + 16384);               // [128][4]
    float* spart = (float*)(smem + 18432);             // [256][5]
#pragma unroll
    for (int s = 0; s < 2; s++) {
        int row = wid * 16 + s * 8 + gid;
#pragma unroll
        for (int q = 0; q < 4; q++) {
            sd[row * 16 + tig * 4 + q] = bd[s][q];
            si[row * 16 + tig * 4 + q] = bi[s][q];
        }
    }
    __syncthreads();
    if (tid < 128) {
        float fb[4]; int fi[4];
#pragma unroll
        for (int q = 0; q < 4; q++) { fb[q] = 3.4e38f; fi[q] = 0; }
        for (int e = 0; e < 16; e++) {
            float dv = sd[tid * 16 + e]; int iv = si[tid * 16 + e];
            if (dv < fb[3]) {
#pragma unroll
                for (int q = 0; q < 4; q++)
                    if (dv < fb[q]) {
                        float tf = fb[q]; int ti = fi[q];
                        fb[q] = dv; fi[q] = iv; dv = tf; iv = ti;
                    }
            }
        }
#pragma unroll
        for (int q = 0; q < 4; q++) scand[tid * 4 + q] = fi[q];
    }
    __syncthreads();

    // ---- exact fp32 rerank (2 threads per point) + x2 + quant/idx write + loss
    int pt = tid & 127, h = tid >> 7;
    int n = n_base + pt;
    const float* lp = latb + pt;
    int c0i = scand[pt * 4 + 0], c1i = scand[pt * 4 + 1];
    int c2i = scand[pt * 4 + 2], c3i = scand[pt * 4 + 3];
    {
        const float* e0 = emb + (size_t)c0i * EDIM;
        const float* e1 = emb + (size_t)c1i * EDIM;
        const float* e2r = emb + (size_t)c2i * EDIM;
        const float* e3 = emb + (size_t)c3i * EDIM;
        float d0 = 0.f, d1 = 0.f, d2 = 0.f, d3 = 0.f, px2 = 0.f;
        int dlo = h * 128, dhi = dlo + 128;
#pragma unroll 4
        for (int d = dlo; d < dhi; d++) {
            float x = lp[(size_t)d * PTS_PER_B];
            d0 = fmaf(x, e0[d], d0);
            d1 = fmaf(x, e1[d], d1);
            d2 = fmaf(x, e2r[d], d2);
            d3 = fmaf(x, e3[d], d3);
            px2 = fmaf(x, x, px2);
        }
        spart[tid * 5 + 0] = d0; spart[tid * 5 + 1] = d1;
        spart[tid * 5 + 2] = d2; spart[tid * 5 + 3] = d3;
        spart[tid * 5 + 4] = px2;
    }
    __syncthreads();

    float D0 = spart[pt * 5 + 0] + spart[(pt + 128) * 5 + 0];
    float D1 = spart[pt * 5 + 1] + spart[(pt + 128) * 5 + 1];
    float D2 = spart[pt * 5 + 2] + spart[(pt + 128) * 5 + 2];
    float D3 = spart[pt * 5 + 3] + spart[(pt + 128) * 5 + 3];
    float X2 = spart[pt * 5 + 4] + spart[(pt + 128) * 5 + 4];

    float best = 3.4e38f; int bk = 0x7fffffff;
    {
        float dd; int kk;
        dd = __fsub_rn(__fadd_rn(X2, g_e2[c0i]), __fmul_rn(2.f, D0)); kk = c0i;
        if (dd < best || (dd == best && kk < bk)) { best = dd; bk = kk; }
        dd = __fsub_rn(__fadd_rn(X2, g_e2[c1i]), __fmul_rn(2.f, D1)); kk = c1i;
        if (dd < best || (dd == best && kk < bk)) { best = dd; bk = kk; }
        dd = __fsub_rn(__fadd_rn(X2, g_e2[c2i]), __fmul_rn(2.f, D2)); kk = c2i;
        if (dd < best || (dd == best && kk < bk)) { best = dd; bk = kk; }
        dd = __fsub_rn(__fadd_rn(X2, g_e2[c3i]), __fmul_rn(2.f, D3)); kk = c3i;
        if (dd < best || (dd == best && kk < bk)) { best = dd; bk = kk; }
    }
    if (h == 0 && full) out[QUANT_ELEMS + 1 + n] = (float)bk;

    // quant write: each thread writes its 128 dims from the emb row (L1 reuse)
    {
        size_t base = (size_t)b * LAT_B_STRIDE + p0 + pt;
        const float* ebr = emb + (size_t)bk * EDIM;
        int dlo = h * 128, dhi = dlo + 128;
#pragma unroll 4
        for (int d = dlo; d < dhi; d++)
            out[base + (size_t)d * PTS_PER_B] = ebr[d];
    }

    // loss: block reduce of best (h==0 only)
    {
        double* sl = (double*)(smem + 28672);
        sl[tid] = (h == 0) ? (double)best : 0.0;
        __syncthreads();
        for (int o = 128; o > 0; o >>= 1) { if (tid < o) sl[tid] += sl[tid + o]; __syncthreads(); }
        if (tid == 0) atomicAdd(&g_loss_sum, sl[0]);
    }
}

__global__ void k_fin(float* out) {
    float m = (float)(g_loss_sum * (1.0 / (double)QUANT_ELEMS));
    out[QUANT_ELEMS] = __fadd_rn(m, __fmul_rn(0.25f, m));
}

// ---------------------------------------------------------------- launch
extern "C" void kernel_launch(void* const* d_in, const int* in_sizes, int n_in,
                              void* d_out, int out_size) {
    const float* lat = (const float*)d_in[0];
    const float* emb = (const float*)d_in[1];
    float* out = (float*)d_out;
    int full = (out_size >= QUANT_ELEMS + 1 + NPTS) ? 1 : 0;

    cudaFuncSetAttribute(k_dist_tc, cudaFuncAttributeMaxDynamicSharedMemorySize, SMEM_P1);

    k_zero<<<1, 1>>>();                                        // 0
    k_prep<<<NEMB, 256>>>(emb);                                // 1
    k_zero<<<1, 1>>>();                                        // 2 (idempotent; keeps dist at slot 3)
    k_dist_tc<<<NPTS / 128, 256, SMEM_P1>>>(lat, emb, out, full); // 3  <- profile slot
    if (full) k_fin<<<1, 1>>>(out);                            // 4
}

// round 16
// speedup vs baseline: 2.1702x; 1.8696x over previous
#include <cuda_runtime.h>
#include <cuda_bf16.h>
#include <cstdint>

// ---------------------------------------------------------------- constants
#define NPTS      65536
#define EDIM      256
#define NEMB      1024
#define PTS_PER_B 1024
#define LAT_B_STRIDE 262144
#define QUANT_ELEMS 16777216

// ---------------------------------------------------------------- scratch
__device__ __nv_bfloat16 g_E[NEMB * EDIM];     // bf16(embedding) [k][d]
__device__ float  g_e2[NEMB];
__device__ double g_loss_sum;

// ---------------------------------------------------------------- helpers
__device__ __forceinline__ uint32_t smem_u32(const void* p) {
    uint32_t a;
    asm("{ .reg .u64 t; cvta.to.shared.u64 t, %1; cvt.u32.u64 %0, t; }" : "=r"(a) : "l"(p));
    return a;
}
__device__ __forceinline__ void cpasync16(uint32_t dst, const void* src) {
    asm volatile("cp.async.cg.shared.global [%0], [%1], 16;" :: "r"(dst), "l"(src));
}
#define CP_COMMIT() asm volatile("cp.async.commit_group;" ::: "memory")
#define CP_WAIT(n)  asm volatile("cp.async.wait_group %0;" :: "n"(n) : "memory")

__device__ __forceinline__ void ldm_x4(uint32_t& r0, uint32_t& r1, uint32_t& r2, uint32_t& r3,
                                       uint32_t addr) {
    asm volatile("ldmatrix.sync.aligned.m8n8.x4.shared.b16 {%0,%1,%2,%3}, [%4];"
        : "=r"(r0), "=r"(r1), "=r"(r2), "=r"(r3) : "r"(addr));
}
__device__ __forceinline__ void mma_bf16(float& c0, float& c1, float& c2, float& c3,
                                         uint32_t a0, uint32_t a1, uint32_t a2, uint32_t a3,
                                         uint32_t b0, uint32_t b1) {
    asm volatile("mma.sync.aligned.m16n8k16.row.col.f32.bf16.bf16.f32 "
        "{%0,%1,%2,%3}, {%4,%5,%6,%7}, {%8,%9}, {%0,%1,%2,%3};"
        : "+f"(c0), "+f"(c1), "+f"(c2), "+f"(c3)
        : "r"(a0), "r"(a1), "r"(a2), "r"(a3), "r"(b0), "r"(b1));
}
__device__ __forceinline__ uint32_t pack_bf16(float lo, float hi) {
    return (uint32_t)__bfloat16_as_ushort(__float2bfloat16(lo))
         | ((uint32_t)__bfloat16_as_ushort(__float2bfloat16(hi)) << 16);
}

// ---------------------------------------------------------------- small kernels
__global__ void k_zero() { g_loss_sum = 0.0; }

__global__ __launch_bounds__(256) void k_prep(const float* __restrict__ emb) {
    int k = blockIdx.x, c = threadIdx.x;
    float v = emb[k * EDIM + c];
    g_E[k * EDIM + c] = __float2bfloat16(v);
    __shared__ float s[256];
    s[c] = v * v;
    __syncthreads();
    for (int o = 128; o > 0; o >>= 1) { if (c < o) s[c] += s[c + o]; __syncthreads(); }
    if (c == 0) g_e2[k] = s[0];
}

// ---------------------------------------------------------------- fused mega-kernel
#define ROWB 528
#define ECH  16896
#define SM_E2   (4 * ECH)           // 67584
#define SMEM_P1 (SM_E2 + 512)       // 68096

__global__ __launch_bounds__(256, 2) void k_dist_tc(const float* __restrict__ lat,
                                                    const float* __restrict__ emb,
                                                    float* __restrict__ out, int full) {
    extern __shared__ char smem[];
    uint32_t sb = smem_u32(smem);
    int tid = threadIdx.x;
    int wid = tid >> 5, l = tid & 31;
    int gid = l >> 2, tig = l & 3;
    int n_base = blockIdx.x * 128;
    int b = n_base >> 10, p0 = n_base & 1023;
    const float* latb = lat + (size_t)b * LAT_B_STRIDE + p0;

    // prologue: issue E chunks 0..3
#pragma unroll
    for (int pc = 0; pc < 4; pc++) {
        for (int i = tid; i < 1024; i += 256) {
            int row = i >> 5, v = i & 31;
            cpasync16(sb + pc * ECH + row * ROWB + v * 16,
                      g_E + (size_t)(pc * 32 + row) * EDIM + v * 8);
        }
        if (tid < 8) cpasync16(sb + SM_E2 + pc * 128 + tid * 16, g_e2 + pc * 32 + tid * 4);
        CP_COMMIT();
    }

    // A fragments straight from fp32 lat (convert to bf16 pairs).
    uint32_t a[16][4];
    {
        int r = l >> 2;
        int c0 = (l & 3) * 2;
        int m0 = wid * 16 + r;
#pragma unroll
        for (int kc = 0; kc < 16; kc++) {
            int cb = kc * 16 + c0;
            float f00 = latb[(size_t)(cb    ) * PTS_PER_B + m0];
            float f01 = latb[(size_t)(cb + 1) * PTS_PER_B + m0];
            float f10 = latb[(size_t)(cb    ) * PTS_PER_B + m0 + 8];
            float f11 = latb[(size_t)(cb + 1) * PTS_PER_B + m0 + 8];
            float f20 = latb[(size_t)(cb + 8) * PTS_PER_B + m0];
            float f21 = latb[(size_t)(cb + 9) * PTS_PER_B + m0];
            float f30 = latb[(size_t)(cb + 8) * PTS_PER_B + m0 + 8];
            float f31 = latb[(size_t)(cb + 9) * PTS_PER_B + m0 + 8];
            a[kc][0] = pack_bf16(f00, f01);
            a[kc][1] = pack_bf16(f10, f11);
            a[kc][2] = pack_bf16(f20, f21);
            a[kc][3] = pack_bf16(f30, f31);
        }
    }

    uint32_t b_off[2];
#pragma unroll
    for (int jj = 0; jj < 2; jj++)
        b_off[jj] = (uint32_t)((jj * 16 + ((l >> 4) & 1) * 8 + (l & 7)) * ROWB
                               + ((l >> 3) & 1) * 16);

    float bd[2][4]; int bi[2][4];
#pragma unroll
    for (int s = 0; s < 2; s++)
#pragma unroll
        for (int q = 0; q < 4; q++) { bd[s][q] = 3.4e38f; bi[s][q] = 0; }

    for (int c = 0; c < 32; c++) {
        int buf = c & 3;
        if (c <= 28) { CP_WAIT(3); }
        else if (c == 29) { CP_WAIT(2); }
        else if (c == 30) { CP_WAIT(1); }
        else { CP_WAIT(0); }
        __syncthreads();

        float acc[4][4];
#pragma unroll
        for (int jt = 0; jt < 4; jt++)
#pragma unroll
            for (int q = 0; q < 4; q++) acc[jt][q] = 0.f;

        uint32_t eb = sb + buf * ECH;
#pragma unroll
        for (int kc = 0; kc < 16; kc++) {
            uint32_t br[2][4];
#pragma unroll
            for (int jj = 0; jj < 2; jj++)
                ldm_x4(br[jj][0], br[jj][1], br[jj][2], br[jj][3], eb + b_off[jj] + kc * 32);
#pragma unroll
            for (int jj = 0; jj < 2; jj++)
#pragma unroll
                for (int h = 0; h < 2; h++)
                    mma_bf16(acc[jj * 2 + h][0], acc[jj * 2 + h][1],
                             acc[jj * 2 + h][2], acc[jj * 2 + h][3],
                             a[kc][0], a[kc][1], a[kc][2], a[kc][3],
                             br[jj][h * 2], br[jj][h * 2 + 1]);
        }

        int nck = c * 32;
        const float2* e2p = (const float2*)(smem + SM_E2 + buf * 128);
#pragma unroll
        for (int jt = 0; jt < 4; jt++) {
            float2 e2v = e2p[jt * 4 + tig];
            int nb0 = nck + jt * 8 + tig * 2;
#pragma unroll
            for (int s = 0; s < 2; s++) {
                float d0 = fmaf(-2.f, acc[jt][s * 2 + 0], e2v.x);
                float d1 = fmaf(-2.f, acc[jt][s * 2 + 1], e2v.y);
                if (d0 < bd[s][3]) {
                    float dv = d0; int iv = nb0;
#pragma unroll
                    for (int q = 0; q < 4; q++)
                        if (dv < bd[s][q]) {
                            float tf = bd[s][q]; int ti = bi[s][q];
                            bd[s][q] = dv; bi[s][q] = iv; dv = tf; iv = ti;
                        }
                }
                if (d1 < bd[s][3]) {
                    float dv = d1; int iv = nb0 + 1;
#pragma unroll
                    for (int q = 0; q < 4; q++)
                        if (dv < bd[s][q]) {
                            float tf = bd[s][q]; int ti = bi[s][q];
                            bd[s][q] = dv; bi[s][q] = iv; dv = tf; iv = ti;
                        }
                }
            }
        }
        __syncthreads();
        int nc = c + 4;
        if (nc < 32) {
            for (int i = tid; i < 1024; i += 256) {
                int row = i >> 5, v = i & 31;
                cpasync16(sb + buf * ECH + row * ROWB + v * 16,
                          g_E + (size_t)(nc * 32 + row) * EDIM + v * 8);
            }
            if (tid < 8) cpasync16(sb + SM_E2 + buf * 128 + tid * 16, g_e2 + nc * 32 + tid * 4);
            CP_COMMIT();
        }
    }

    // ---- merge per-row top-4 across the 4 tig lanes
    __syncthreads();
    float* sd    = (float*)(smem);
    int*   si    = (int*)(smem + 8192);
    int*   scand = (int*)(smem + 16384);               // [128][4]
    float* spart = (float*)(smem + 18432);             // [256][5]
#pragma unroll
    for (int s = 0; s < 2; s++) {
        int row = wid * 16 + s * 8 + gid;
#pragma unroll
        for (int q = 0; q < 4; q++) {
            sd[row * 16 + tig * 4 + q] = bd[s][q];
            si[row * 16 + tig * 4 + q] = bi[s][q];
        }
    }
    __syncthreads();
    if (tid < 128) {
        float fb[4]; int fi[4];
#pragma unroll
        for (int q = 0; q < 4; q++) { fb[q] = 3.4e38f; fi[q] = 0; }
        for (int e = 0; e < 16; e++) {
            float dv = sd[tid * 16 + e]; int iv = si[tid * 16 + e];
            if (dv < fb[3]) {
#pragma unroll
                for (int q = 0; q < 4; q++)
                    if (dv < fb[q]) {
                        float tf = fb[q]; int ti = fi[q];
                        fb[q] = dv; fi[q] = iv; dv = tf; iv = ti;
                    }
            }
        }
#pragma unroll
        for (int q = 0; q < 4; q++) scand[tid * 4 + q] = fi[q];
    }
    __syncthreads();

    // ---- exact fp32 rerank (2 threads/point) with float4 row gathers
    int pt = tid & 127, h = tid >> 7;
    int n = n_base + pt;
    const float* lp = latb + pt;
    int c0i = scand[pt * 4 + 0], c1i = scand[pt * 4 + 1];
    int c2i = scand[pt * 4 + 2], c3i = scand[pt * 4 + 3];
    {
        const float* e0 = emb + (size_t)c0i * EDIM;
        const float* e1 = emb + (size_t)c1i * EDIM;
        const float* e2r = emb + (size_t)c2i * EDIM;
        const float* e3 = emb + (size_t)c3i * EDIM;
        float d0 = 0.f, d1 = 0.f, d2 = 0.f, d3 = 0.f, px2 = 0.f;
        int dlo = h * 128;
#pragma unroll 4
        for (int dq = 0; dq < 32; dq++) {
            int d = dlo + dq * 4;
            float4 v0 = *(const float4*)(e0 + d);
            float4 v1 = *(const float4*)(e1 + d);
            float4 v2 = *(const float4*)(e2r + d);
            float4 v3 = *(const float4*)(e3 + d);
            float x0 = lp[(size_t)(d + 0) * PTS_PER_B];
            float x1 = lp[(size_t)(d + 1) * PTS_PER_B];
            float x2 = lp[(size_t)(d + 2) * PTS_PER_B];
            float x3 = lp[(size_t)(d + 3) * PTS_PER_B];
            d0 = fmaf(x0, v0.x, d0); d0 = fmaf(x1, v0.y, d0);
            d0 = fmaf(x2, v0.z, d0); d0 = fmaf(x3, v0.w, d0);
            d1 = fmaf(x0, v1.x, d1); d1 = fmaf(x1, v1.y, d1);
            d1 = fmaf(x2, v1.z, d1); d1 = fmaf(x3, v1.w, d1);
            d2 = fmaf(x0, v2.x, d2); d2 = fmaf(x1, v2.y, d2);
            d2 = fmaf(x2, v2.z, d2); d2 = fmaf(x3, v2.w, d2);
            d3 = fmaf(x0, v3.x, d3); d3 = fmaf(x1, v3.y, d3);
            d3 = fmaf(x2, v3.z, d3); d3 = fmaf(x3, v3.w, d3);
            px2 = fmaf(x0, x0, px2); px2 = fmaf(x1, x1, px2);
            px2 = fmaf(x2, x2, px2); px2 = fmaf(x3, x3, px2);
        }
        spart[tid * 5 + 0] = d0; spart[tid * 5 + 1] = d1;
        spart[tid * 5 + 2] = d2; spart[tid * 5 + 3] = d3;
        spart[tid * 5 + 4] = px2;
    }
    __syncthreads();

    float D0 = spart[pt * 5 + 0] + spart[(pt + 128) * 5 + 0];
    float D1 = spart[pt * 5 + 1] + spart[(pt + 128) * 5 + 1];
    float D2 = spart[pt * 5 + 2] + spart[(pt + 128) * 5 + 2];
    float D3 = spart[pt * 5 + 3] + spart[(pt + 128) * 5 + 3];
    float X2 = spart[pt * 5 + 4] + spart[(pt + 128) * 5 + 4];

    float best = 3.4e38f; int bk = 0x7fffffff;
    {
        float dd; int kk;
        dd = __fsub_rn(__fadd_rn(X2, g_e2[c0i]), __fmul_rn(2.f, D0)); kk = c0i;
        if (dd < best || (dd == best && kk < bk)) { best = dd; bk = kk; }
        dd = __fsub_rn(__fadd_rn(X2, g_e2[c1i]), __fmul_rn(2.f, D1)); kk = c1i;
        if (dd < best || (dd == best && kk < bk)) { best = dd; bk = kk; }
        dd = __fsub_rn(__fadd_rn(X2, g_e2[c2i]), __fmul_rn(2.f, D2)); kk = c2i;
        if (dd < best || (dd == best && kk < bk)) { best = dd; bk = kk; }
        dd = __fsub_rn(__fadd_rn(X2, g_e2[c3i]), __fmul_rn(2.f, D3)); kk = c3i;
        if (dd < best || (dd == best && kk < bk)) { best = dd; bk = kk; }
    }
    if (h == 0 && full) out[QUANT_ELEMS + 1 + n] = (float)bk;

    // quant write: float4 row read, scalar coalesced column stores
    {
        size_t base = (size_t)b * LAT_B_STRIDE + p0 + pt;
        const float* ebr = emb + (size_t)bk * EDIM;
        int dlo = h * 128;
#pragma unroll 4
        for (int dq = 0; dq < 32; dq++) {
            int d = dlo + dq * 4;
            float4 qv = *(const float4*)(ebr + d);
            out[base + (size_t)(d + 0) * PTS_PER_B] = qv.x;
            out[base + (size_t)(d + 1) * PTS_PER_B] = qv.y;
            out[base + (size_t)(d + 2) * PTS_PER_B] = qv.z;
            out[base + (size_t)(d + 3) * PTS_PER_B] = qv.w;
        }
    }

    // loss: block reduce of best (h==0 only)
    {
        double* sl = (double*)(smem + 28672);
        sl[tid] = (h == 0) ? (double)best : 0.0;
        __syncthreads();
        for (int o = 128; o > 0; o >>= 1) { if (tid < o) sl[tid] += sl[tid + o]; __syncthreads(); }
        if (tid == 0) atomicAdd(&g_loss_sum, sl[0]);
    }
}

__global__ void k_fin(float* out) {
    float m = (float)(g_loss_sum * (1.0 / (double)QUANT_ELEMS));
    out[QUANT_ELEMS] = __fadd_rn(m, __fmul_rn(0.25f, m));
}

// ---------------------------------------------------------------- launch
extern "C" void kernel_launch(void* const* d_in, const int* in_sizes, int n_in,
                              void* d_out, int out_size) {
    const float* lat = (const float*)d_in[0];
    const float* emb = (const float*)d_in[1];
    float* out = (float*)d_out;
    int full = (out_size >= QUANT_ELEMS + 1 + NPTS) ? 1 : 0;

    cudaFuncSetAttribute(k_dist_tc, cudaFuncAttributeMaxDynamicSharedMemorySize, SMEM_P1);

    k_zero<<<1, 1>>>();                                           // 0
    k_prep<<<NEMB, 256>>>(emb);                                   // 1
    k_zero<<<1, 1>>>();                                           // 2 (idempotent)
    k_dist_tc<<<NPTS / 128, 256, SMEM_P1>>>(lat, emb, out, full); // 3  <- profile slot
    if (full) k_fin<<<1, 1>>>(out);                               // 4
}

// round 17
// speedup vs baseline: 2.3480x; 1.0819x over previous
#include <cuda_runtime.h>
#include <cuda_bf16.h>
#include <cstdint>

// ---------------------------------------------------------------- constants
#define NPTS      65536
#define EDIM      256
#define NEMB      1024
#define PTS_PER_B 1024
#define LAT_B_STRIDE 262144
#define QUANT_ELEMS 16777216

// ---------------------------------------------------------------- scratch
__device__ __nv_bfloat16 g_E[NEMB * EDIM];     // bf16(embedding) [k][d]
__device__ float  g_e2[NEMB];
__device__ double g_loss_sum;

// ---------------------------------------------------------------- helpers
__device__ __forceinline__ uint32_t smem_u32(const void* p) {
    uint32_t a;
    asm("{ .reg .u64 t; cvta.to.shared.u64 t, %1; cvt.u32.u64 %0, t; }" : "=r"(a) : "l"(p));
    return a;
}
__device__ __forceinline__ void cpasync16(uint32_t dst, const void* src) {
    asm volatile("cp.async.cg.shared.global [%0], [%1], 16;" :: "r"(dst), "l"(src));
}
#define CP_COMMIT() asm volatile("cp.async.commit_group;" ::: "memory")
#define CP_WAIT(n)  asm volatile("cp.async.wait_group %0;" :: "n"(n) : "memory")

__device__ __forceinline__ void ldm_x4(uint32_t& r0, uint32_t& r1, uint32_t& r2, uint32_t& r3,
                                       uint32_t addr) {
    asm volatile("ldmatrix.sync.aligned.m8n8.x4.shared.b16 {%0,%1,%2,%3}, [%4];"
        : "=r"(r0), "=r"(r1), "=r"(r2), "=r"(r3) : "r"(addr));
}
__device__ __forceinline__ void mma_bf16(float& c0, float& c1, float& c2, float& c3,
                                         uint32_t a0, uint32_t a1, uint32_t a2, uint32_t a3,
                                         uint32_t b0, uint32_t b1) {
    asm volatile("mma.sync.aligned.m16n8k16.row.col.f32.bf16.bf16.f32 "
        "{%0,%1,%2,%3}, {%4,%5,%6,%7}, {%8,%9}, {%0,%1,%2,%3};"
        : "+f"(c0), "+f"(c1), "+f"(c2), "+f"(c3)
        : "r"(a0), "r"(a1), "r"(a2), "r"(a3), "r"(b0), "r"(b1));
}
__device__ __forceinline__ uint32_t pack_bf16(float lo, float hi) {
    return (uint32_t)__bfloat16_as_ushort(__float2bfloat16(lo))
         | ((uint32_t)__bfloat16_as_ushort(__float2bfloat16(hi)) << 16);
}

// ---------------------------------------------------------------- small kernels
__global__ void k_zero() { g_loss_sum = 0.0; }

__global__ __launch_bounds__(256) void k_prep(const float* __restrict__ emb) {
    int k = blockIdx.x, c = threadIdx.x;
    float v = emb[k * EDIM + c];
    g_E[k * EDIM + c] = __float2bfloat16(v);
    __shared__ float s[256];
    s[c] = v * v;
    __syncthreads();
    for (int o = 128; o > 0; o >>= 1) { if (c < o) s[c] += s[c + o]; __syncthreads(); }
    if (c == 0) g_e2[k] = s[0];
}

// ---------------------------------------------------------------- fused mega-kernel
// mainloop smem: E ring 4 x 16896 + e2 4 x 128
// epilogue smem: stage sF[128][132] f32 (67584) reuses ring; scand/spart/sbk above.
#define ROWB 528
#define ECH  16896
#define SM_E2    (4 * ECH)          // 67584
#define OFF_CAND 68096              // int [128][4]   (2048 B)
#define OFF_PART 70144              // float [128][5] (2560 B)
#define OFF_BK   72704              // int [128]      (512 B)
#define SMEM_P1  73216
#define CP 132                      // stage pad (floats per point row)

__global__ __launch_bounds__(256, 2) void k_dist_tc(const float* __restrict__ lat,
                                                    const float* __restrict__ emb,
                                                    float* __restrict__ out, int full) {
    extern __shared__ char smem[];
    uint32_t sb = smem_u32(smem);
    int tid = threadIdx.x;
    int wid = tid >> 5, l = tid & 31;
    int gid = l >> 2, tig = l & 3;
    int n_base = blockIdx.x * 128;
    int b = n_base >> 10, p0 = n_base & 1023;
    const float* latb = lat + (size_t)b * LAT_B_STRIDE + p0;

    // prologue: issue E chunks 0..3
#pragma unroll
    for (int pc = 0; pc < 4; pc++) {
        for (int i = tid; i < 1024; i += 256) {
            int row = i >> 5, v = i & 31;
            cpasync16(sb + pc * ECH + row * ROWB + v * 16,
                      g_E + (size_t)(pc * 32 + row) * EDIM + v * 8);
        }
        if (tid < 8) cpasync16(sb + SM_E2 + pc * 128 + tid * 16, g_e2 + pc * 32 + tid * 4);
        CP_COMMIT();
    }

    // A fragments straight from fp32 lat (convert to bf16 pairs).
    uint32_t a[16][4];
    {
        int r = l >> 2;
        int c0 = (l & 3) * 2;
        int m0 = wid * 16 + r;
#pragma unroll
        for (int kc = 0; kc < 16; kc++) {
            int cb = kc * 16 + c0;
            float f00 = latb[(size_t)(cb    ) * PTS_PER_B + m0];
            float f01 = latb[(size_t)(cb + 1) * PTS_PER_B + m0];
            float f10 = latb[(size_t)(cb    ) * PTS_PER_B + m0 + 8];
            float f11 = latb[(size_t)(cb + 1) * PTS_PER_B + m0 + 8];
            float f20 = latb[(size_t)(cb + 8) * PTS_PER_B + m0];
            float f21 = latb[(size_t)(cb + 9) * PTS_PER_B + m0];
            float f30 = latb[(size_t)(cb + 8) * PTS_PER_B + m0 + 8];
            float f31 = latb[(size_t)(cb + 9) * PTS_PER_B + m0 + 8];
            a[kc][0] = pack_bf16(f00, f01);
            a[kc][1] = pack_bf16(f10, f11);
            a[kc][2] = pack_bf16(f20, f21);
            a[kc][3] = pack_bf16(f30, f31);
        }
    }

    uint32_t b_off[2];
#pragma unroll
    for (int jj = 0; jj < 2; jj++)
        b_off[jj] = (uint32_t)((jj * 16 + ((l >> 4) & 1) * 8 + (l & 7)) * ROWB
                               + ((l >> 3) & 1) * 16);

    float bd[2][4]; int bi[2][4];
#pragma unroll
    for (int s = 0; s < 2; s++)
#pragma unroll
        for (int q = 0; q < 4; q++) { bd[s][q] = 3.4e38f; bi[s][q] = 0; }

    for (int c = 0; c < 32; c++) {
        int buf = c & 3;
        if (c <= 28) { CP_WAIT(3); }
        else if (c == 29) { CP_WAIT(2); }
        else if (c == 30) { CP_WAIT(1); }
        else { CP_WAIT(0); }
        __syncthreads();

        float acc[4][4];
#pragma unroll
        for (int jt = 0; jt < 4; jt++)
#pragma unroll
            for (int q = 0; q < 4; q++) acc[jt][q] = 0.f;

        uint32_t eb = sb + buf * ECH;
#pragma unroll
        for (int kc = 0; kc < 16; kc++) {
            uint32_t br[2][4];
#pragma unroll
            for (int jj = 0; jj < 2; jj++)
                ldm_x4(br[jj][0], br[jj][1], br[jj][2], br[jj][3], eb + b_off[jj] + kc * 32);
#pragma unroll
            for (int jj = 0; jj < 2; jj++)
#pragma unroll
                for (int h = 0; h < 2; h++)
                    mma_bf16(acc[jj * 2 + h][0], acc[jj * 2 + h][1],
                             acc[jj * 2 + h][2], acc[jj * 2 + h][3],
                             a[kc][0], a[kc][1], a[kc][2], a[kc][3],
                             br[jj][h * 2], br[jj][h * 2 + 1]);
        }

        int nck = c * 32;
        const float2* e2p = (const float2*)(smem + SM_E2 + buf * 128);
#pragma unroll
        for (int jt = 0; jt < 4; jt++) {
            float2 e2v = e2p[jt * 4 + tig];
            int nb0 = nck + jt * 8 + tig * 2;
#pragma unroll
            for (int s = 0; s < 2; s++) {
                float d0 = fmaf(-2.f, acc[jt][s * 2 + 0], e2v.x);
                float d1 = fmaf(-2.f, acc[jt][s * 2 + 1], e2v.y);
                if (d0 < bd[s][3]) {
                    float dv = d0; int iv = nb0;
#pragma unroll
                    for (int q = 0; q < 4; q++)
                        if (dv < bd[s][q]) {
                            float tf = bd[s][q]; int ti = bi[s][q];
                            bd[s][q] = dv; bi[s][q] = iv; dv = tf; iv = ti;
                        }
                }
                if (d1 < bd[s][3]) {
                    float dv = d1; int iv = nb0 + 1;
#pragma unroll
                    for (int q = 0; q < 4; q++)
                        if (dv < bd[s][q]) {
                            float tf = bd[s][q]; int ti = bi[s][q];
                            bd[s][q] = dv; bi[s][q] = iv; dv = tf; iv = ti;
                        }
                }
            }
        }
        __syncthreads();
        int nc = c + 4;
        if (nc < 32) {
            for (int i = tid; i < 1024; i += 256) {
                int row = i >> 5, v = i & 31;
                cpasync16(sb + buf * ECH + row * ROWB + v * 16,
                          g_E + (size_t)(nc * 32 + row) * EDIM + v * 8);
            }
            if (tid < 8) cpasync16(sb + SM_E2 + buf * 128 + tid * 16, g_e2 + nc * 32 + tid * 4);
            CP_COMMIT();
        }
    }

    // ---- Phase A: merge per-row top-4 across the 4 tig lanes
    __syncthreads();
    float* sd    = (float*)(smem);
    int*   si    = (int*)(smem + 8192);
    int*   scand = (int*)(smem + OFF_CAND);
    float* spart = (float*)(smem + OFF_PART);
    int*   sbk   = (int*)(smem + OFF_BK);
    float* sF    = (float*)(smem);               // stage area (reuses ring)
#pragma unroll
    for (int s = 0; s < 2; s++) {
        int row = wid * 16 + s * 8 + gid;
#pragma unroll
        for (int q = 0; q < 4; q++) {
            sd[row * 16 + tig * 4 + q] = bd[s][q];
            si[row * 16 + tig * 4 + q] = bi[s][q];
        }
    }
    __syncthreads();
    if (tid < 128) {
        float fb[4]; int fi[4];
#pragma unroll
        for (int q = 0; q < 4; q++) { fb[q] = 3.4e38f; fi[q] = 0; }
        for (int e = 0; e < 16; e++) {
            float dv = sd[tid * 16 + e]; int iv = si[tid * 16 + e];
            if (dv < fb[3]) {
#pragma unroll
                for (int q = 0; q < 4; q++)
                    if (dv < fb[q]) {
                        float tf = fb[q]; int ti = fi[q];
                        fb[q] = dv; fi[q] = iv; dv = tf; iv = ti;
                    }
            }
        }
#pragma unroll
        for (int q = 0; q < 4; q++) scand[tid * 4 + q] = fi[q];
    }

    // ---- Phase B: exact fp32 rerank, warp-per-point, lat staged in smem
    for (int half = 0; half < 2; half++) {
        __syncthreads();   // scand ready / previous dots done
        // stage lat half: sF[pt][d'] <- latb[(half*128+d')*1024 + pt]  (coalesced reads)
        for (int i = 0; i < 64; i++) {
            int e = i * 256 + tid;
            int dd = e >> 7, pt = e & 127;
            sF[pt * CP + dd] = latb[(size_t)(half * 128 + dd) * PTS_PER_B + pt];
        }
        __syncthreads();
        // warp w handles points w*16 .. w*16+15
        for (int pp = 0; pp < 16; pp++) {
            int pt = wid * 16 + pp;
            int cc0 = scand[pt * 4 + 0], cc1 = scand[pt * 4 + 1];
            int cc2 = scand[pt * 4 + 2], cc3 = scand[pt * 4 + 3];
            float4 xl = *(const float4*)(sF + pt * CP + l * 4);
            int eoff = half * 128 + l * 4;
            float4 v0 = *(const float4*)(emb + (size_t)cc0 * EDIM + eoff);
            float4 v1 = *(const float4*)(emb + (size_t)cc1 * EDIM + eoff);
            float4 v2 = *(const float4*)(emb + (size_t)cc2 * EDIM + eoff);
            float4 v3 = *(const float4*)(emb + (size_t)cc3 * EDIM + eoff);
            float p0v = fmaf(xl.w, v0.w, fmaf(xl.z, v0.z, fmaf(xl.y, v0.y, xl.x * v0.x)));
            float p1v = fmaf(xl.w, v1.w, fmaf(xl.z, v1.z, fmaf(xl.y, v1.y, xl.x * v1.x)));
            float p2v = fmaf(xl.w, v2.w, fmaf(xl.z, v2.z, fmaf(xl.y, v2.y, xl.x * v2.x)));
            float p3v = fmaf(xl.w, v3.w, fmaf(xl.z, v3.z, fmaf(xl.y, v3.y, xl.x * v3.x)));
            float px2 = fmaf(xl.w, xl.w, fmaf(xl.z, xl.z, fmaf(xl.y, xl.y, xl.x * xl.x)));
#pragma unroll
            for (int o = 16; o > 0; o >>= 1) {
                p0v += __shfl_xor_sync(0xffffffffu, p0v, o);
                p1v += __shfl_xor_sync(0xffffffffu, p1v, o);
                p2v += __shfl_xor_sync(0xffffffffu, p2v, o);
                p3v += __shfl_xor_sync(0xffffffffu, p3v, o);
                px2 += __shfl_xor_sync(0xffffffffu, px2, o);
            }
            if (l == 0) {
                if (half == 0) {
                    spart[pt * 5 + 0] = p0v; spart[pt * 5 + 1] = p1v;
                    spart[pt * 5 + 2] = p2v; spart[pt * 5 + 3] = p3v;
                    spart[pt * 5 + 4] = px2;
                } else {
                    spart[pt * 5 + 0] += p0v; spart[pt * 5 + 1] += p1v;
                    spart[pt * 5 + 2] += p2v; spart[pt * 5 + 3] += p3v;
                    spart[pt * 5 + 4] += px2;
                }
            }
        }
    }
    __syncthreads();

    // finalize argmin per point (reference rounding + lowest-index tie-break)
    if (tid < 128) {
        int pt = tid;
        int cids[4];
#pragma unroll
        for (int q = 0; q < 4; q++) cids[q] = scand[pt * 4 + q];
        float X2 = spart[pt * 5 + 4];
        float best = 3.4e38f; int bk = 0x7fffffff;
#pragma unroll
        for (int q = 0; q < 4; q++) {
            int kk = cids[q];
            float dd = __fsub_rn(__fadd_rn(X2, g_e2[kk]),
                                 __fmul_rn(2.f, spart[pt * 5 + q]));
            if (dd < best || (dd == best && kk < bk)) { best = dd; bk = kk; }
        }
        sbk[pt] = bk;
        spart[pt * 5 + 4] = best;      // stash best dist for loss
        if (full) out[QUANT_ELEMS + 1 + n_base + pt] = (float)bk;
    }

    // ---- Phase C: quant write via smem bounce (coalesced both sides)
    for (int half = 0; half < 2; half++) {
        __syncthreads();
        for (int pp = 0; pp < 16; pp++) {
            int pt = wid * 16 + pp;
            int bk = sbk[pt];
            float4 ev = *(const float4*)(emb + (size_t)bk * EDIM + half * 128 + l * 4);
            *(float4*)(sF + pt * CP + l * 4) = ev;
        }
        __syncthreads();
        size_t obase = (size_t)b * LAT_B_STRIDE + p0;
        for (int i = 0; i < 64; i++) {
            int e = i * 256 + tid;
            int dd = e >> 7, pt = e & 127;
            out[obase + (size_t)(half * 128 + dd) * PTS_PER_B + pt] = sF[pt * CP + dd];
        }
    }

    // ---- loss: block reduce of best dists
    __syncthreads();
    {
        double* sl = (double*)(smem);   // stage area free now
        sl[tid] = (tid < 128) ? (double)spart[tid * 5 + 4] : 0.0;
        __syncthreads();
        for (int o = 128; o > 0; o >>= 1) { if (tid < o) sl[tid] += sl[tid + o]; __syncthreads(); }
        if (tid == 0) atomicAdd(&g_loss_sum, sl[0]);
    }
}

__global__ void k_fin(float* out) {
    float m = (float)(g_loss_sum * (1.0 / (double)QUANT_ELEMS));
    out[QUANT_ELEMS] = __fadd_rn(m, __fmul_rn(0.25f, m));
}

// ---------------------------------------------------------------- launch
extern "C" void kernel_launch(void* const* d_in, const int* in_sizes, int n_in,
                              void* d_out, int out_size) {
    const float* lat = (const float*)d_in[0];
    const float* emb = (const float*)d_in[1];
    float* out = (float*)d_out;
    int full = (out_size >= QUANT_ELEMS + 1 + NPTS) ? 1 : 0;

    cudaFuncSetAttribute(k_dist_tc, cudaFuncAttributeMaxDynamicSharedMemorySize, SMEM_P1);

    k_zero<<<1, 1>>>();                                           // 0
    k_prep<<<NEMB, 256>>>(emb);                                   // 1
    k_zero<<<1, 1>>>();                                           // 2 (idempotent)
    k_dist_tc<<<NPTS / 128, 256, SMEM_P1>>>(lat, emb, out, full); // 3  <- profile slot
    if (full) k_fin<<<1, 1>>>(out);                               // 4
}